// round 16
// baseline (speedup 1.0000x reference)
#include <cuda_runtime.h>
#include <math.h>

#define BATCH 128
#define CHN   3
#define IMH   135
#define IMW   240
#define NCH   (BATCH * CHN)
#define EPSV  1e-10f

typedef unsigned long long u64;

// ---------------- packed f32x2 helpers (sm_103a) ---------------------------
__device__ __forceinline__ u64 pk(float lo, float hi) {
    u64 r; asm("mov.b64 %0, {%1,%2};" : "=l"(r) : "f"(lo), "f"(hi)); return r;
}
__device__ __forceinline__ void upk(u64 v, float& lo, float& hi) {
    asm("mov.b64 {%0,%1}, %2;" : "=f"(lo), "=f"(hi) : "l"(v));
}
__device__ __forceinline__ u64 fma2(u64 a, u64 b, u64 c) {
    u64 d; asm("fma.rn.f32x2 %0, %1, %2, %3;" : "=l"(d) : "l"(a), "l"(b), "l"(c)); return d;
}
__device__ __forceinline__ u64 mul2(u64 a, u64 b) {
    u64 d; asm("mul.rn.f32x2 %0, %1, %2;" : "=l"(d) : "l"(a), "l"(b)); return d;
}
__device__ __forceinline__ u64 add2(u64 a, u64 b) {
    u64 d; asm("add.rn.f32x2 %0, %1, %2;" : "=l"(d) : "l"(a), "l"(b)); return d;
}
// (a.hi, b.lo) — odd-tap pair from two neighboring even pairs
__device__ __forceinline__ u64 mid(u64 a, u64 b) {
    float al, ah, bl, bh; upk(a, al, ah); upk(b, bl, bh); return pk(ah, bl);
}
// one conv tap into the 5 packed accumulators
__device__ __forceinline__ void tap5(u64 w, u64 rv, u64 pv,
                                     u64& ar, u64& ap, u64& arr, u64& app, u64& arp) {
    u64 tr = mul2(w, rv), tp = mul2(w, pv);
    ar = add2(ar, tr); ap = add2(ap, tp);
    arr = fma2(tr, rv, arr); app = fma2(tp, pv, app); arp = fma2(tr, pv, arp);
}

// ---------------- scratch (device globals — no allocation) ----------------
__device__ float g_num[NCH];
__device__ float g_den[NCH];
__device__ float g_dot[BATCH];
__device__ u64   g_w2[4][9];   // packed (w,w); symmetric half j=0..(N-1)/2

// ---------------- init: zero accumulators + weights every launch -----------
__global__ void init_kernel() {
    int i = threadIdx.x;
    if (i < NCH)   { g_num[i] = 0.0f; g_den[i] = 0.0f; }
    if (i < BATCH) { g_dot[i] = 0.0f; }
    if (i == 0) {
        const int Ns[4] = {17, 9, 5, 3};
        for (int s = 0; s < 4; s++) {
            int n = Ns[s];
            float sigma  = (float)n / 5.0f;
            float inv2s2 = 1.0f / (2.0f * sigma * sigma);
            float wv[17];
            float sum = 0.0f;
            for (int j = 0; j < n; j++) {
                float d = (float)(j - n / 2);
                float v = expf(-d * d * inv2s2);
                wv[j] = v;
                sum += v;
            }
            float is = 1.0f / sum;
            for (int j = 0; j < (n + 1) / 2; j++) {
                float w = wv[j] * is;
                g_w2[s][j] = pk(w, w);
            }
        }
    }
}

// ================= shared vertical + pointwise + reduction =================
template <int N>
__device__ __forceinline__ void vertical_and_reduce(
    const u64* __restrict__ ww, ulonglong2* hA, ulonglong2* hB, u64* hC,
    float* red, int tid, int lane, int yg, int ch, int ox0, int oy0,
    int nwarps
) {
    constexpr int KY  = 2;
    constexpr int HO  = IMH - N + 1;
    constexpr int WO  = IMW - N + 1;
    constexpr int HLF = (N - 1) / 2;

    const int y0 = yg * KY;
    u64 am1[KY], am2[KY], vrr[KY], vpp[KY], vrp[KY];
    #pragma unroll
    for (int k = 0; k < KY; k++) { am1[k] = 0; am2[k] = 0; vrr[k] = 0; vpp[k] = 0; vrp[k] = 0; }

    #pragma unroll
    for (int t = 0; t < KY + N - 1; t++) {
        int row = y0 + t;
        ulonglong2 A = hA[row * 16 + lane];
        ulonglong2 B = hB[row * 16 + lane];
        u64        C = hC[row * 16 + lane];
        #pragma unroll
        for (int k = 0; k < KY; k++) {
            int j = t - k;
            if (j >= 0 && j < N) {
                u64 w = ww[(j <= HLF) ? j : (N - 1 - j)];
                am1[k] = fma2(w, A.x, am1[k]);
                am2[k] = fma2(w, A.y, am2[k]);
                vrr[k] = fma2(w, B.x, vrr[k]);
                vpp[k] = fma2(w, B.y, vpp[k]);
                vrp[k] = fma2(w, C,   vrp[k]);
            }
        }
    }

    float prodN = 1.0f, prodD = 1.0f;
    const int oxb = ox0 + 2 * lane;
    #pragma unroll
    for (int k = 0; k < KY; k++) {
        if (oy0 + y0 + k >= HO) continue;
        float m1[2], m2[2], rr[2], pp[2], rp[2];
        upk(am1[k], m1[0], m1[1]);
        upk(am2[k], m2[0], m2[1]);
        upk(vrr[k], rr[0], rr[1]);
        upk(vpp[k], pp[0], pp[1]);
        upk(vrp[k], rp[0], rp[1]);
        #pragma unroll
        for (int c = 0; c < 2; c++) {
            if (oxb + c >= WO) continue;
            float sGT = fmaxf(rr[c] - m1[c] * m1[c], 0.0f);
            float sP  = fmaxf(pp[c] - m2[c] * m2[c], 0.0f);
            float sGP = rp[c] - m1[c] * m2[c];
            // num != 0 only when all reference masks are un-triggered
            bool cond = (sGT >= EPSV) && (sP >= EPSV) && (sGP > 0.0f);
            float g  = cond ? __fdividef(sGP, sGT + EPSV) : 0.0f;
            float sv = fmaxf(sP - g * sGP, EPSV);
            prodN *= fmaf(g * g, __fdividef(sGT, sv + 2.0f), 1.0f);
            // den: sGT<EPS -> 1+sGT/2 rounds to 1.0f -> contributes 0, same
            prodD *= fmaf(sGT, 0.5f, 1.0f);
        }
    }
    float numa = __log2f(prodN);   // log10 scale cancels in num/den ratio
    float dena = __log2f(prodD);

    #pragma unroll
    for (int o = 16; o > 0; o >>= 1) {
        numa += __shfl_down_sync(0xFFFFFFFFu, numa, o);
        dena += __shfl_down_sync(0xFFFFFFFFu, dena, o);
    }
    if ((tid & 31) == 0) {
        red[tid >> 5]        = numa;
        red[16 + (tid >> 5)] = dena;
    }
    __syncthreads();
    if (tid == 0) {
        float n = 0.f, d = 0.f;
        for (int w = 0; w < nwarps; w++) { n += red[w]; d += red[16 + w]; }
        atomicAdd(&g_num[ch], n);
        atomicAdd(&g_den[ch], d);
    }
}

// ================= staged kernel (N=17 only) ================================
// 384 threads = 16 lanes (2 adjacent x outputs, f32x2) x 24 y-groups, TY=48.
template <int N, int SIDX>
__global__ __launch_bounds__(384)
void vif_scale(const float* __restrict__ R, const float* __restrict__ P) {
    constexpr int NYG = 24;
    constexpr int TY  = NYG * 2;         // 48
    constexpr int IH  = TY + N - 1;
    constexpr int IW  = 32 + N - 1;
    constexpr int IWH = IW / 2;
    constexpr int HLF = (N - 1) / 2;
    constexpr int NH  = (N + 1) / 2;

    extern __shared__ __align__(16) char SM[];
    float4*     s4  = (float4*)SM;
    ulonglong2* hA  = (ulonglong2*)(SM + 16 * IH * IWH);
    ulonglong2* hB  = hA + IH * 16;
    u64*        hC  = (u64*)(hB + IH * 16);
    float*      red = (float*)(hC + IH * 16);

    const int tid  = threadIdx.x;
    const int lane = tid & 15;
    const int yg   = tid >> 4;
    const int ch   = blockIdx.z;
    const int ox0  = blockIdx.x * 32;
    const int oy0  = blockIdx.y * TY;

    u64 ww[NH];
    #pragma unroll
    for (int j = 0; j < NH; j++) ww[j] = g_w2[SIDX][j];

    const float* __restrict__ r = R + (size_t)ch * (IMH * IMW);
    const float* __restrict__ p = P + (size_t)ch * (IMH * IMW);
    for (int idx = tid; idx < IH * IWH; idx += 384) {
        int row = idx / IWH, c2 = idx - row * IWH;
        int gy = oy0 + row, gx = ox0 + 2 * c2;
        u64 rv = 0ull, pv = 0ull;
        if (gy < IMH && gx < IMW) {
            int o = gy * IMW + gx;
            rv = *(const u64*)&r[o];
            pv = *(const u64*)&p[o];
        }
        float4 st;
        upk(rv, st.x, st.y);
        upk(pv, st.z, st.w);
        s4[idx] = st;
    }
    __syncthreads();

    for (int row = yg; row < IH; row += NYG) {
        const int base2 = row * IWH + lane;
        float4 F = s4[base2];
        u64 rl = pk(F.x, F.y);
        u64 pl = pk(F.z, F.w);
        u64 ar, ap, arr, app, arp;
        {
            u64 w  = ww[0];
            u64 tr = mul2(w, rl), tp = mul2(w, pl);
            ar = tr; ap = tp;
            arr = mul2(tr, rl); app = mul2(tp, pl); arp = mul2(tr, pl);
        }
        #pragma unroll
        for (int j2 = 2; j2 < N; j2 += 2) {
            float4 G = s4[base2 + j2 / 2];
            u64 rn = pk(G.x, G.y);
            u64 pn = pk(G.z, G.w);
            tap5(ww[(j2 <= HLF) ? j2 : (N - 1 - j2)], rn, pn, ar, ap, arr, app, arp);
            {
                int jm = j2 - 1;
                u64 w  = ww[(jm <= HLF) ? jm : (N - 1 - jm)];
                tap5(w, mid(rl, rn), mid(pl, pn), ar, ap, arr, app, arp);
            }
            rl = rn; pl = pn;
        }
        hA[row * 16 + lane] = make_ulonglong2(ar, ap);
        hB[row * 16 + lane] = make_ulonglong2(arr, app);
        hC[row * 16 + lane] = arp;
    }
    __syncthreads();

    vertical_and_reduce<N>(ww, hA, hB, hC, red, tid, lane, yg, ch, ox0, oy0, 12);
}

// ============ direct-global kernel (N=9 / N=5 / N=3) =======================
// Horizontal taps read straight from gmem (L1/L2-resident). Hoisted clamp:
// gxb is even and IMW-N is odd, so any pair with a valid output has
// gxb <= IMW-N-1, making every tap load in-bounds unclamped; a single
// min(gxb, IMW-N-1) (even, alignment-preserving) handles fully-discarded
// pairs. Rows clamp once per row. smem holds only the 5 horizontal planes.
template <int N, int SIDX>
__global__ __launch_bounds__(384)
void vif_scale_dg(const float* __restrict__ R, const float* __restrict__ P) {
    constexpr int NYG = 24;
    constexpr int TY  = NYG * 2;         // 48
    constexpr int IH  = TY + N - 1;
    constexpr int HLF = (N - 1) / 2;
    constexpr int NH  = (N + 1) / 2;

    extern __shared__ __align__(16) char SM[];
    ulonglong2* hA  = (ulonglong2*)SM;
    ulonglong2* hB  = hA + IH * 16;
    u64*        hC  = (u64*)(hB + IH * 16);
    float*      red = (float*)(hC + IH * 16);

    const int tid  = threadIdx.x;
    const int lane = tid & 15;
    const int yg   = tid >> 4;
    const int ch   = blockIdx.z;
    const int ox0  = blockIdx.x * 32;
    const int oy0  = blockIdx.y * TY;

    u64 ww[NH];
    #pragma unroll
    for (int j = 0; j < NH; j++) ww[j] = g_w2[SIDX][j];

    const float* __restrict__ r = R + (size_t)ch * (IMH * IMW);
    const float* __restrict__ p = P + (size_t)ch * (IMH * IMW);
    const int gxb = ox0 + 2 * lane;                  // even
    const int o0  = min(gxb, IMW - N - 1);           // even; all taps in-bounds

    // ---- horizontal pass straight from gmem (no per-tap clamp) ----
    for (int row = yg; row < IH; row += NYG) {
        int gy = min(oy0 + row, IMH - 1);            // row clamp (discarded rows)
        const float* __restrict__ rrow = r + gy * IMW + o0;
        const float* __restrict__ prow = p + gy * IMW + o0;

        u64 rl = *(const u64*)&rrow[0];
        u64 pl = *(const u64*)&prow[0];
        u64 ar, ap, arr, app, arp;
        {
            u64 w  = ww[0];
            u64 tr = mul2(w, rl), tp = mul2(w, pl);
            ar = tr; ap = tp;
            arr = mul2(tr, rl); app = mul2(tp, pl); arp = mul2(tr, pl);
        }
        #pragma unroll
        for (int j2 = 2; j2 < N; j2 += 2) {
            u64 rn = *(const u64*)&rrow[j2];
            u64 pn = *(const u64*)&prow[j2];
            tap5(ww[(j2 <= HLF) ? j2 : (N - 1 - j2)], rn, pn, ar, ap, arr, app, arp);
            {
                int jm = j2 - 1;
                u64 w  = ww[(jm <= HLF) ? jm : (N - 1 - jm)];
                tap5(w, mid(rl, rn), mid(pl, pn), ar, ap, arr, app, arp);
            }
            rl = rn; pl = pn;
        }
        hA[row * 16 + lane] = make_ulonglong2(ar, ap);
        hB[row * 16 + lane] = make_ulonglong2(arr, app);
        hC[row * 16 + lane] = arp;
    }
    __syncthreads();

    vertical_and_reduce<N>(ww, hA, hB, hC, red, tid, lane, yg, ch, ox0, oy0, 12);
}

// ---------------- prediction term: per-image dot((x - r), W) ---------------
__global__ __launch_bounds__(1024)
void pred_kernel(const float* __restrict__ R, const float* __restrict__ X,
                 const float* __restrict__ Wl) {
    const int img = blockIdx.x;
    const int n4  = (CHN * IMH * IMW) / 4;  // 24300
    const float4* r4 = (const float4*)(R + (size_t)img * (CHN * IMH * IMW));
    const float4* x4 = (const float4*)(X + (size_t)img * (CHN * IMH * IMW));
    const float4* w4 = (const float4*)Wl;
    float acc = 0.0f;
    for (int i = threadIdx.x; i < n4; i += 1024) {
        float4 a = x4[i], b = r4[i], w = w4[i];
        acc = fmaf(a.x - b.x, w.x, acc);
        acc = fmaf(a.y - b.y, w.y, acc);
        acc = fmaf(a.z - b.z, w.z, acc);
        acc = fmaf(a.w - b.w, w.w, acc);
    }
    __shared__ float red[32];
    #pragma unroll
    for (int o = 16; o > 0; o >>= 1)
        acc += __shfl_down_sync(0xFFFFFFFFu, acc, o);
    if ((threadIdx.x & 31) == 0) red[threadIdx.x >> 5] = acc;
    __syncthreads();
    if (threadIdx.x < 32) {
        float v = red[threadIdx.x];
        #pragma unroll
        for (int o = 16; o > 0; o >>= 1)
            v += __shfl_down_sync(0xFFFFFFFFu, v, o);
        if (threadIdx.x == 0) g_dot[img] = v;
    }
}

// ---------------- final: assemble the 3 scalars ----------------------------
__global__ void final_kernel(float* __restrict__ out) {
    const int t = threadIdx.x;  // 128 threads, one per image
    float vif = 0.0f;
    #pragma unroll
    for (int c = 0; c < CHN; c++) {
        int ch = t * CHN + c;
        vif += g_num[ch] / g_den[ch];
    }
    vif *= (1.0f / CHN);
    float rl = 1.0f - vif;
    float d  = g_dot[t];
    float pl = d * d;

    __shared__ float red[8];
    #pragma unroll
    for (int o = 16; o > 0; o >>= 1) {
        rl += __shfl_down_sync(0xFFFFFFFFu, rl, o);
        pl += __shfl_down_sync(0xFFFFFFFFu, pl, o);
    }
    if ((t & 31) == 0) {
        red[t >> 5]       = rl;
        red[4 + (t >> 5)] = pl;
    }
    __syncthreads();
    if (t == 0) {
        float rls = 0.f, pls = 0.f;
        #pragma unroll
        for (int w = 0; w < 4; w++) { rls += red[w]; pls += red[4 + w]; }
        rls *= (1.0f / BATCH);
        pls *= (1.0f / BATCH);
        out[0] = pls + rls;  // loss
        out[1] = rls;        // recons_loss
        out[2] = pls;        // prediction_loss
    }
}

// ---------------- launch ---------------------------------------------------
static inline int smb_g(int N) {      // staged kernel, TY=48
    int IH = N + 47, IW = 32 + N - 1;
    return 8 * IH * IW + 640 * IH + 128;
}
static inline int smb_dg(int N) {     // direct-global kernel: planes only
    int IH = N + 47;
    return 640 * IH + 128;
}

extern "C" void kernel_launch(void* const* d_in, const int* in_sizes, int n_in,
                              void* d_out, int out_size) {
    const float* recons = (const float*)d_in[0];
    const float* x      = (const float*)d_in[1];
    const float* Wl     = (const float*)d_in[2];
    // d_in[3] = b, cancels exactly in (pred_orig - pred_recons)
    float* out = (float*)d_out;

    // opt-in to >48KB dynamic smem (attribute set, not an allocation)
    cudaFuncSetAttribute(vif_scale<17, 0>,
                         cudaFuncAttributeMaxDynamicSharedMemorySize, smb_g(17));

    init_kernel<<<1, 384>>>();

    dim3 blk(384);
    // N=17: staged. out 119x224 -> grid 7x3, smem 65664, 3 blk/SM (36 warps)
    vif_scale<17, 0><<<dim3(7, 3, NCH), blk, smb_g(17)>>>(recons, x);
    // N=9: direct-global. out 127x232 -> grid 8x3, smem 35968
    vif_scale_dg< 9, 1><<<dim3(8, 3, NCH), blk, smb_dg(9)>>>(recons, x);
    // N=5: direct-global. out 131x236 -> grid 8x3, smem 33408
    vif_scale_dg< 5, 2><<<dim3(8, 3, NCH), blk, smb_dg(5)>>>(recons, x);
    // N=3: direct-global. out 133x238 -> grid 8x3, smem 32128
    vif_scale_dg< 3, 3><<<dim3(8, 3, NCH), blk, smb_dg(3)>>>(recons, x);

    pred_kernel<<<BATCH, 1024>>>(recons, x, Wl);
    final_kernel<<<1, 128>>>(out);
}

// round 17
// speedup vs baseline: 1.0885x; 1.0885x over previous
#include <cuda_runtime.h>
#include <math.h>

#define BATCH 128
#define CHN   3
#define IMH   135
#define IMW   240
#define NCH   (BATCH * CHN)
#define EPSV  1e-10f

typedef unsigned long long u64;

// ---------------- packed f32x2 helpers (sm_103a) ---------------------------
__device__ __forceinline__ u64 pk(float lo, float hi) {
    u64 r; asm("mov.b64 %0, {%1,%2};" : "=l"(r) : "f"(lo), "f"(hi)); return r;
}
__device__ __forceinline__ void upk(u64 v, float& lo, float& hi) {
    asm("mov.b64 {%0,%1}, %2;" : "=f"(lo), "=f"(hi) : "l"(v));
}
__device__ __forceinline__ u64 fma2(u64 a, u64 b, u64 c) {
    u64 d; asm("fma.rn.f32x2 %0, %1, %2, %3;" : "=l"(d) : "l"(a), "l"(b), "l"(c)); return d;
}
__device__ __forceinline__ u64 mul2(u64 a, u64 b) {
    u64 d; asm("mul.rn.f32x2 %0, %1, %2;" : "=l"(d) : "l"(a), "l"(b)); return d;
}
__device__ __forceinline__ u64 add2(u64 a, u64 b) {
    u64 d; asm("add.rn.f32x2 %0, %1, %2;" : "=l"(d) : "l"(a), "l"(b)); return d;
}
// (a.hi, b.lo) — odd-tap pair from two neighboring even pairs
__device__ __forceinline__ u64 mid(u64 a, u64 b) {
    float al, ah, bl, bh; upk(a, al, ah); upk(b, bl, bh); return pk(ah, bl);
}
// one conv tap into the 5 packed accumulators
__device__ __forceinline__ void tap5(u64 w, u64 rv, u64 pv,
                                     u64& ar, u64& ap, u64& arr, u64& app, u64& arp) {
    u64 tr = mul2(w, rv), tp = mul2(w, pv);
    ar = add2(ar, tr); ap = add2(ap, tp);
    arr = fma2(tr, rv, arr); app = fma2(tp, pv, app); arp = fma2(tr, pv, arp);
}

// ---------------- scratch (device globals — no allocation) ----------------
__device__ float g_num[NCH];
__device__ float g_den[NCH];
__device__ float g_dot[BATCH];
__device__ u64   g_w2[4][9];   // packed (w,w); symmetric half j=0..(N-1)/2

// ---------------- init: zero accumulators + weights every launch -----------
__global__ void init_kernel() {
    int i = threadIdx.x;
    if (i < NCH)   { g_num[i] = 0.0f; g_den[i] = 0.0f; }
    if (i < BATCH) { g_dot[i] = 0.0f; }
    if (i == 0) {
        const int Ns[4] = {17, 9, 5, 3};
        for (int s = 0; s < 4; s++) {
            int n = Ns[s];
            float sigma  = (float)n / 5.0f;
            float inv2s2 = 1.0f / (2.0f * sigma * sigma);
            float wv[17];
            float sum = 0.0f;
            for (int j = 0; j < n; j++) {
                float d = (float)(j - n / 2);
                float v = expf(-d * d * inv2s2);
                wv[j] = v;
                sum += v;
            }
            float is = 1.0f / sum;
            for (int j = 0; j < (n + 1) / 2; j++) {
                float w = wv[j] * is;
                g_w2[s][j] = pk(w, w);
            }
        }
    }
}

// ================= shared vertical + pointwise + reduction =================
template <int N>
__device__ __forceinline__ void vertical_and_reduce(
    const u64* __restrict__ ww, ulonglong2* hA, ulonglong2* hB, u64* hC,
    float* red, int tid, int lane, int yg, int ch, int ox0, int oy0,
    int nwarps
) {
    constexpr int KY  = 2;
    constexpr int HO  = IMH - N + 1;
    constexpr int WO  = IMW - N + 1;
    constexpr int HLF = (N - 1) / 2;

    const int y0 = yg * KY;
    u64 am1[KY], am2[KY], vrr[KY], vpp[KY], vrp[KY];
    #pragma unroll
    for (int k = 0; k < KY; k++) { am1[k] = 0; am2[k] = 0; vrr[k] = 0; vpp[k] = 0; vrp[k] = 0; }

    #pragma unroll
    for (int t = 0; t < KY + N - 1; t++) {
        int row = y0 + t;
        ulonglong2 A = hA[row * 16 + lane];
        ulonglong2 B = hB[row * 16 + lane];
        u64        C = hC[row * 16 + lane];
        #pragma unroll
        for (int k = 0; k < KY; k++) {
            int j = t - k;
            if (j >= 0 && j < N) {
                u64 w = ww[(j <= HLF) ? j : (N - 1 - j)];
                am1[k] = fma2(w, A.x, am1[k]);
                am2[k] = fma2(w, A.y, am2[k]);
                vrr[k] = fma2(w, B.x, vrr[k]);
                vpp[k] = fma2(w, B.y, vpp[k]);
                vrp[k] = fma2(w, C,   vrp[k]);
            }
        }
    }

    float prodN = 1.0f, prodD = 1.0f;
    const int oxb = ox0 + 2 * lane;
    #pragma unroll
    for (int k = 0; k < KY; k++) {
        if (oy0 + y0 + k >= HO) continue;
        float m1[2], m2[2], rr[2], pp[2], rp[2];
        upk(am1[k], m1[0], m1[1]);
        upk(am2[k], m2[0], m2[1]);
        upk(vrr[k], rr[0], rr[1]);
        upk(vpp[k], pp[0], pp[1]);
        upk(vrp[k], rp[0], rp[1]);
        #pragma unroll
        for (int c = 0; c < 2; c++) {
            if (oxb + c >= WO) continue;
            float sGT = fmaxf(rr[c] - m1[c] * m1[c], 0.0f);
            float sP  = fmaxf(pp[c] - m2[c] * m2[c], 0.0f);
            float sGP = rp[c] - m1[c] * m2[c];
            // num != 0 only when all reference masks are un-triggered
            bool cond = (sGT >= EPSV) && (sP >= EPSV) && (sGP > 0.0f);
            float g  = cond ? __fdividef(sGP, sGT + EPSV) : 0.0f;
            float sv = fmaxf(sP - g * sGP, EPSV);
            prodN *= fmaf(g * g, __fdividef(sGT, sv + 2.0f), 1.0f);
            // den: sGT<EPS -> 1+sGT/2 rounds to 1.0f -> contributes 0, same
            prodD *= fmaf(sGT, 0.5f, 1.0f);
        }
    }
    float numa = __log2f(prodN);   // log10 scale cancels in num/den ratio
    float dena = __log2f(prodD);

    #pragma unroll
    for (int o = 16; o > 0; o >>= 1) {
        numa += __shfl_down_sync(0xFFFFFFFFu, numa, o);
        dena += __shfl_down_sync(0xFFFFFFFFu, dena, o);
    }
    if ((tid & 31) == 0) {
        red[tid >> 5]        = numa;
        red[16 + (tid >> 5)] = dena;
    }
    __syncthreads();
    if (tid == 0) {
        float n = 0.f, d = 0.f;
        for (int w = 0; w < nwarps; w++) { n += red[w]; d += red[16 + w]; }
        atomicAdd(&g_num[ch], n);
        atomicAdd(&g_den[ch], d);
    }
}

// ============ direct-global kernel (all scales) ============================
// Horizontal taps read straight from gmem (L1/L2-resident). Hoisted clamp:
// gxb is even and IMW-N-1 is even, so min(gxb, IMW-N-1) keeps u64 alignment
// and makes every tap load in-bounds; clamped pairs feed only discarded
// outputs. Rows clamp once per row. smem holds only the 5 horizontal planes.
template <int N, int SIDX>
__global__ __launch_bounds__(384)
void vif_scale_dg(const float* __restrict__ R, const float* __restrict__ P) {
    constexpr int NYG = 24;
    constexpr int TY  = NYG * 2;         // 48
    constexpr int IH  = TY + N - 1;
    constexpr int HLF = (N - 1) / 2;
    constexpr int NH  = (N + 1) / 2;

    extern __shared__ __align__(16) char SM[];
    ulonglong2* hA  = (ulonglong2*)SM;
    ulonglong2* hB  = hA + IH * 16;
    u64*        hC  = (u64*)(hB + IH * 16);
    float*      red = (float*)(hC + IH * 16);

    const int tid  = threadIdx.x;
    const int lane = tid & 15;
    const int yg   = tid >> 4;
    const int ch   = blockIdx.z;
    const int ox0  = blockIdx.x * 32;
    const int oy0  = blockIdx.y * TY;

    u64 ww[NH];
    #pragma unroll
    for (int j = 0; j < NH; j++) ww[j] = g_w2[SIDX][j];

    const float* __restrict__ r = R + (size_t)ch * (IMH * IMW);
    const float* __restrict__ p = P + (size_t)ch * (IMH * IMW);
    const int gxb = ox0 + 2 * lane;                  // even
    const int o0  = min(gxb, IMW - N - 1);           // even; all taps in-bounds

    // ---- horizontal pass straight from gmem (no per-tap clamp) ----
    for (int row = yg; row < IH; row += NYG) {
        int gy = min(oy0 + row, IMH - 1);            // row clamp (discarded rows)
        const float* __restrict__ rrow = r + gy * IMW + o0;
        const float* __restrict__ prow = p + gy * IMW + o0;

        u64 rl = *(const u64*)&rrow[0];
        u64 pl = *(const u64*)&prow[0];
        u64 ar, ap, arr, app, arp;
        {
            u64 w  = ww[0];
            u64 tr = mul2(w, rl), tp = mul2(w, pl);
            ar = tr; ap = tp;
            arr = mul2(tr, rl); app = mul2(tp, pl); arp = mul2(tr, pl);
        }
        #pragma unroll
        for (int j2 = 2; j2 < N; j2 += 2) {
            u64 rn = *(const u64*)&rrow[j2];
            u64 pn = *(const u64*)&prow[j2];
            tap5(ww[(j2 <= HLF) ? j2 : (N - 1 - j2)], rn, pn, ar, ap, arr, app, arp);
            {
                int jm = j2 - 1;
                u64 w  = ww[(jm <= HLF) ? jm : (N - 1 - jm)];
                tap5(w, mid(rl, rn), mid(pl, pn), ar, ap, arr, app, arp);
            }
            rl = rn; pl = pn;
        }
        hA[row * 16 + lane] = make_ulonglong2(ar, ap);
        hB[row * 16 + lane] = make_ulonglong2(arr, app);
        hC[row * 16 + lane] = arp;
    }
    __syncthreads();

    vertical_and_reduce<N>(ww, hA, hB, hC, red, tid, lane, yg, ch, ox0, oy0, 12);
}

// ---------------- prediction term: per-image dot((x - r), W) ---------------
__global__ __launch_bounds__(1024)
void pred_kernel(const float* __restrict__ R, const float* __restrict__ X,
                 const float* __restrict__ Wl) {
    const int img = blockIdx.x;
    const int n4  = (CHN * IMH * IMW) / 4;  // 24300
    const float4* r4 = (const float4*)(R + (size_t)img * (CHN * IMH * IMW));
    const float4* x4 = (const float4*)(X + (size_t)img * (CHN * IMH * IMW));
    const float4* w4 = (const float4*)Wl;
    float acc = 0.0f;
    for (int i = threadIdx.x; i < n4; i += 1024) {
        float4 a = x4[i], b = r4[i], w = w4[i];
        acc = fmaf(a.x - b.x, w.x, acc);
        acc = fmaf(a.y - b.y, w.y, acc);
        acc = fmaf(a.z - b.z, w.z, acc);
        acc = fmaf(a.w - b.w, w.w, acc);
    }
    __shared__ float red[32];
    #pragma unroll
    for (int o = 16; o > 0; o >>= 1)
        acc += __shfl_down_sync(0xFFFFFFFFu, acc, o);
    if ((threadIdx.x & 31) == 0) red[threadIdx.x >> 5] = acc;
    __syncthreads();
    if (threadIdx.x < 32) {
        float v = red[threadIdx.x];
        #pragma unroll
        for (int o = 16; o > 0; o >>= 1)
            v += __shfl_down_sync(0xFFFFFFFFu, v, o);
        if (threadIdx.x == 0) g_dot[img] = v;
    }
}

// ---------------- final: assemble the 3 scalars ----------------------------
__global__ void final_kernel(float* __restrict__ out) {
    const int t = threadIdx.x;  // 128 threads, one per image
    float vif = 0.0f;
    #pragma unroll
    for (int c = 0; c < CHN; c++) {
        int ch = t * CHN + c;
        vif += g_num[ch] / g_den[ch];
    }
    vif *= (1.0f / CHN);
    float rl = 1.0f - vif;
    float d  = g_dot[t];
    float pl = d * d;

    __shared__ float red[8];
    #pragma unroll
    for (int o = 16; o > 0; o >>= 1) {
        rl += __shfl_down_sync(0xFFFFFFFFu, rl, o);
        pl += __shfl_down_sync(0xFFFFFFFFu, pl, o);
    }
    if ((t & 31) == 0) {
        red[t >> 5]       = rl;
        red[4 + (t >> 5)] = pl;
    }
    __syncthreads();
    if (t == 0) {
        float rls = 0.f, pls = 0.f;
        #pragma unroll
        for (int w = 0; w < 4; w++) { rls += red[w]; pls += red[4 + w]; }
        rls *= (1.0f / BATCH);
        pls *= (1.0f / BATCH);
        out[0] = pls + rls;  // loss
        out[1] = rls;        // recons_loss
        out[2] = pls;        // prediction_loss
    }
}

// ---------------- launch ---------------------------------------------------
static inline int smb_dg(int N) {     // direct-global kernel: planes only
    int IH = N + 47;
    return 640 * IH + 128;
}

extern "C" void kernel_launch(void* const* d_in, const int* in_sizes, int n_in,
                              void* d_out, int out_size) {
    const float* recons = (const float*)d_in[0];
    const float* x      = (const float*)d_in[1];
    const float* Wl     = (const float*)d_in[2];
    // d_in[3] = b, cancels exactly in (pred_orig - pred_recons)
    float* out = (float*)d_out;

    init_kernel<<<1, 384>>>();

    dim3 blk(384);
    // All scales direct-global, TY=48 -> grid.y = 3.
    // N=17: out 119x224 -> grid 7x3, smem 41088 (<48KB, no opt-in needed)
    vif_scale_dg<17, 0><<<dim3(7, 3, NCH), blk, smb_dg(17)>>>(recons, x);
    // N=9:  out 127x232 -> grid 8x3, smem 35968
    vif_scale_dg< 9, 1><<<dim3(8, 3, NCH), blk, smb_dg(9)>>>(recons, x);
    // N=5:  out 131x236 -> grid 8x3, smem 33408
    vif_scale_dg< 5, 2><<<dim3(8, 3, NCH), blk, smb_dg(5)>>>(recons, x);
    // N=3:  out 133x238 -> grid 8x3, smem 32128
    vif_scale_dg< 3, 3><<<dim3(8, 3, NCH), blk, smb_dg(3)>>>(recons, x);

    pred_kernel<<<BATCH, 1024>>>(recons, x, Wl);
    final_kernel<<<1, 128>>>(out);
}